// round 7
// baseline (speedup 1.0000x reference)
#include <cuda_runtime.h>
#include <cuda_bf16.h>
#include <cstdint>

#define HID 1024
#define HEADS 16
#define HD 64
#define BATCH 8
#define SEQ 1024
#define MROWS (BATCH * SEQ)

// ---------------- scratch (device globals; no allocation allowed) ----------
__device__ __nv_bfloat16 g_Qh[MROWS * HID];
__device__ __nv_bfloat16 g_Ql[MROWS * HID];
__device__ __nv_bfloat16 g_Kh[MROWS * HID];
__device__ __nv_bfloat16 g_Kl[MROWS * HID];
__device__ __nv_bfloat16 g_Vh[MROWS * HID];
__device__ __nv_bfloat16 g_Vl[MROWS * HID];
__device__ __nv_bfloat16 g_Ahi[MROWS * HID];
__device__ __nv_bfloat16 g_Alo[MROWS * HID];
__device__ __nv_bfloat16 g_Wqh[HID * HID];
__device__ __nv_bfloat16 g_Wql[HID * HID];
__device__ __nv_bfloat16 g_Wkh[HID * HID];
__device__ __nv_bfloat16 g_Wkl[HID * HID];
__device__ __nv_bfloat16 g_Wvh[HID * HID];
__device__ __nv_bfloat16 g_Wvl[HID * HID];
__device__ __nv_bfloat16 g_Woh[HID * HID];
__device__ __nv_bfloat16 g_Wol[HID * HID];
__device__ float g_invf[HID / 2];
__device__ float4 g_tab[SEQ * (HID / 2)];

// ---------------- helpers ----------------------------------------
__device__ __forceinline__ uint32_t smem_u32(const void* p) {
    uint32_t a;
    asm("{ .reg .u64 t; cvta.to.shared.u64 t, %1; cvt.u32.u64 %0, t; }"
        : "=r"(a) : "l"(p));
    return a;
}
__device__ __forceinline__ void cp16(uint32_t dst, const void* src) {
    asm volatile("cp.async.cg.shared.global [%0], [%1], 16;" :: "r"(dst), "l"(src));
}
#define CP_COMMIT() asm volatile("cp.async.commit_group;" ::: "memory")
#define CP_WAIT1()  asm volatile("cp.async.wait_group 1;" ::: "memory")
#define CP_WAIT2()  asm volatile("cp.async.wait_group 2;" ::: "memory")

__device__ __forceinline__ void ldm4(uint32_t* r, uint32_t addr) {
    asm volatile("ldmatrix.sync.aligned.m8n8.x4.shared.b16 {%0,%1,%2,%3}, [%4];"
                 : "=r"(r[0]), "=r"(r[1]), "=r"(r[2]), "=r"(r[3]) : "r"(addr));
}
__device__ __forceinline__ void ldm4t(uint32_t* r, uint32_t addr) {
    asm volatile("ldmatrix.sync.aligned.m8n8.x4.trans.shared.b16 {%0,%1,%2,%3}, [%4];"
                 : "=r"(r[0]), "=r"(r[1]), "=r"(r[2]), "=r"(r[3]) : "r"(addr));
}
__device__ __forceinline__ void mma16816(float* d, const uint32_t* a,
                                         uint32_t b0, uint32_t b1) {
    asm volatile(
        "mma.sync.aligned.m16n8k16.row.col.f32.bf16.bf16.f32 "
        "{%0,%1,%2,%3}, {%4,%5,%6,%7}, {%8,%9}, {%0,%1,%2,%3};"
        : "+f"(d[0]), "+f"(d[1]), "+f"(d[2]), "+f"(d[3])
        : "r"(a[0]), "r"(a[1]), "r"(a[2]), "r"(a[3]), "r"(b0), "r"(b1));
}
__device__ __forceinline__ void split2(float x, float y, uint32_t& hi, uint32_t& lo) {
    __nv_bfloat162 h = __floats2bfloat162_rn(x, y);
    float2 f = __bfloat1622float2(h);
    __nv_bfloat162 l2 = __floats2bfloat162_rn(x - f.x, y - f.y);
    hi = *reinterpret_cast<uint32_t*>(&h);
    lo = *reinterpret_cast<uint32_t*>(&l2);
}
__device__ __forceinline__ void split8(const float4& u, const float4& v,
                                       uint4& hi, uint4& lo) {
    split2(u.x, u.y, hi.x, lo.x);
    split2(u.z, u.w, hi.y, lo.y);
    split2(v.x, v.y, hi.z, lo.z);
    split2(v.z, v.w, hi.w, lo.w);
}
// permutation: n' = 128p + 64s + i  ->  orig = 64p + 512s + i
__device__ __forceinline__ int perm_orig(int n) {
    int p = n >> 7, s = (n >> 6) & 1, i = n & 63;
    return 64 * p + 512 * s + i;
}

// ============================================================================
// prep kernels
// ============================================================================
__global__ __launch_bounds__(256) void split_act_kernel(
    const float* __restrict__ src, __nv_bfloat16* __restrict__ hi,
    __nv_bfloat16* __restrict__ lo)
{
    int idx = blockIdx.x * 256 + threadIdx.x;   // MROWS*HID/8
    float4 u = ((const float4*)src)[2 * idx];
    float4 v = ((const float4*)src)[2 * idx + 1];
    uint4 h, l;
    split8(u, v, h, l);
    ((uint4*)hi)[idx] = h;
    ((uint4*)lo)[idx] = l;
}

__global__ __launch_bounds__(256) void prep_w_rowperm(
    const float* __restrict__ W, __nv_bfloat16* __restrict__ Wh,
    __nv_bfloat16* __restrict__ Wl)
{
    int idx = blockIdx.x * 256 + threadIdx.x;
    int n = idx >> 7;
    int c8 = (idx & 127) * 8;
    int orig = perm_orig(n);
    float4 u = *(const float4*)(W + (size_t)orig * HID + c8);
    float4 v = *(const float4*)(W + (size_t)orig * HID + c8 + 4);
    uint4 hi, lo;
    split8(u, v, hi, lo);
    *(uint4*)(Wh + (size_t)n * HID + c8) = hi;
    *(uint4*)(Wl + (size_t)n * HID + c8) = lo;
}

__global__ __launch_bounds__(256) void prep_w_colperm(
    const float* __restrict__ W, __nv_bfloat16* __restrict__ Wh,
    __nv_bfloat16* __restrict__ Wl)
{
    int idx = blockIdx.x * 256 + threadIdx.x;
    int n = idx >> 7;
    int k8 = (idx & 127) * 8;
    int orig = perm_orig(k8);
    float4 u = *(const float4*)(W + (size_t)n * HID + orig);
    float4 v = *(const float4*)(W + (size_t)n * HID + orig + 4);
    uint4 hi, lo;
    split8(u, v, hi, lo);
    *(uint4*)(Wh + (size_t)n * HID + k8) = hi;
    *(uint4*)(Wl + (size_t)n * HID + k8) = lo;
}

__global__ void make_invf_kernel() {
    int j = threadIdx.x;
    if (j < HID / 2) {
        double e = exp(-((double)(2 * j) / (double)HID) * log(10000.0));
        g_invf[j] = (float)e;
    }
}
__global__ __launch_bounds__(256) void rope_table_kernel() {
    int idx = blockIdx.x * 256 + threadIdx.x;
    int s = idx >> 9;
    int j = idx & 511;
    float t = (float)s * g_invf[j];
    float st, ct;
    sincosf(t, &st, &ct);
    float s1, c1, s2, c2;
    sincosf(st, &s1, &c1);
    sincosf(ct, &s2, &c2);
    g_tab[idx] = make_float4(c1, s1, c2, s2);
}

// ============================================================================
// unified cp.async-pipelined GEMM (NT): Y = A*B^T, 3-term bf16-split.
// CTA 128x128, warp 64x32, K-chunk 32, 4-stage cp.async ring.
// ROPE=true: epilogue bias+RoPE+scale -> bf16 splits. ROPE=false: bias -> f32.
// ============================================================================
#define RSTRIDE 80
#define TILE_B (128 * RSTRIDE)      // 10240
#define STAGE_B (4 * TILE_B)        // 40960
#define NSTAGE 4
#define GEMM_SMEM (NSTAGE * STAGE_B) // 163840
#define SROW 132

__device__ __forceinline__ void gemm_issue_stage(
    const __nv_bfloat16* a0, const __nv_bfloat16* a1,
    const __nv_bfloat16* b0, const __nv_bfloat16* b1,
    int kc, uint32_t st, int tid)
{
    const size_t ko = (size_t)kc * 32;
#pragma unroll
    for (int i = 0; i < 8; i++) {
        const __nv_bfloat16* g = (i < 2) ? a0 : (i < 4) ? a1 : (i < 6) ? b0 : b1;
        const int t = i >> 1;
        const int rem = ((i & 1) << 8) + tid;
        const int row = rem >> 2;
        const int c = rem & 3;
        cp16(st + t * TILE_B + row * RSTRIDE + c * 16,
             g + (size_t)row * HID + ko + c * 8);
    }
}

template <bool ROPE>
__global__ __launch_bounds__(256)
void gemm_pipe(const __nv_bfloat16* __restrict__ Ah, const __nv_bfloat16* __restrict__ Al,
               const __nv_bfloat16* __restrict__ Bh, const __nv_bfloat16* __restrict__ Bl,
               const float* __restrict__ bias,
               __nv_bfloat16* __restrict__ outh, __nv_bfloat16* __restrict__ outl,
               float* __restrict__ Yf, float scale)
{
    extern __shared__ __align__(128) char smem[];

    const int tid  = threadIdx.x;
    const int wid  = tid >> 5;
    const int lane = tid & 31;
    const int wm   = wid & 1;
    const int wn   = wid >> 1;
    const int brow = blockIdx.y * 128;
    const int bcol = blockIdx.x * 128;

    const uint32_t sbase = smem_u32(smem);
    const uint32_t aoff = (uint32_t)(((lane & 7) + ((lane >> 3) & 1) * 8) * RSTRIDE
                                     + ((lane >> 4) & 1) * 16);
    const uint32_t boff = (uint32_t)(((lane & 7) + ((lane >> 4) & 1) * 8) * RSTRIDE
                                     + ((lane >> 3) & 1) * 16);

    const __nv_bfloat16* a0 = Ah + (size_t)brow * HID;
    const __nv_bfloat16* a1 = Al + (size_t)brow * HID;
    const __nv_bfloat16* b0 = Bh + (size_t)bcol * HID;
    const __nv_bfloat16* b1 = Bl + (size_t)bcol * HID;

    // prologue: 3 stages in flight
#pragma unroll
    for (int p = 0; p < 3; p++) {
        gemm_issue_stage(a0, a1, b0, b1, p, sbase + p * STAGE_B, tid);
        CP_COMMIT();
    }

    float acc[4][4][4];
#pragma unroll
    for (int i = 0; i < 4; i++)
#pragma unroll
        for (int j = 0; j < 4; j++)
#pragma unroll
            for (int r = 0; r < 4; r++) acc[i][j][r] = 0.0f;

    for (int kc = 0; kc < 32; kc++) {
        const int s = kc & 3;
        CP_WAIT2();
        __syncthreads();

        const uint32_t base = sbase + s * STAGE_B;
#pragma unroll
        for (int ks = 0; ks < 2; ks++) {
            const uint32_t kb = ks * 32;
            uint32_t ah[4][4], al[4][4];
#pragma unroll
            for (int mf = 0; mf < 4; mf++) {
                uint32_t ro = (uint32_t)((wm * 64 + mf * 16) * RSTRIDE) + kb;
                ldm4(ah[mf], base + ro + aoff);
                ldm4(al[mf], base + TILE_B + ro + aoff);
            }
            uint32_t bh[2][4], bl[2][4];
#pragma unroll
            for (int p = 0; p < 2; p++) {
                uint32_t ro = (uint32_t)((wn * 32 + p * 16) * RSTRIDE) + kb;
                ldm4(bh[p], base + 2 * TILE_B + ro + boff);
                ldm4(bl[p], base + 3 * TILE_B + ro + boff);
            }
#pragma unroll
            for (int mf = 0; mf < 4; mf++) {
#pragma unroll
                for (int nf = 0; nf < 4; nf++) {
                    const int p = nf >> 1, q = nf & 1;
                    mma16816(acc[mf][nf], ah[mf], bh[p][2 * q], bh[p][2 * q + 1]);
                    mma16816(acc[mf][nf], ah[mf], bl[p][2 * q], bl[p][2 * q + 1]);
                    mma16816(acc[mf][nf], al[mf], bh[p][2 * q], bh[p][2 * q + 1]);
                }
            }
        }
        __syncthreads();
        if (kc + 3 < 32)
            gemm_issue_stage(a0, a1, b0, b1, kc + 3,
                             sbase + ((kc + 3) & 3) * STAGE_B, tid);
        CP_COMMIT();
    }

    const int g  = lane >> 2;
    const int t2 = (lane & 3) * 2;

    if (!ROPE) {
#pragma unroll
        for (int mf = 0; mf < 4; mf++) {
            const int row0 = brow + wm * 64 + mf * 16 + g;
#pragma unroll
            for (int nf = 0; nf < 4; nf++) {
                const int col = bcol + wn * 32 + nf * 8 + t2;
                float2 bv = *(const float2*)(bias + col);
                *(float2*)(Yf + (size_t)row0 * HID + col) =
                    make_float2(acc[mf][nf][0] + bv.x, acc[mf][nf][1] + bv.y);
                *(float2*)(Yf + (size_t)(row0 + 8) * HID + col) =
                    make_float2(acc[mf][nf][2] + bv.x, acc[mf][nf][3] + bv.y);
            }
        }
        return;
    }

    // ROPE epilogue: stage fp32 tile in smem, apply bias + rope + scale
    float* sm = (float*)smem;
#pragma unroll
    for (int mf = 0; mf < 4; mf++) {
        const int lr = wm * 64 + mf * 16 + g;
#pragma unroll
        for (int nf = 0; nf < 4; nf++) {
            const int lc = wn * 32 + nf * 8 + t2;
            *(float2*)(sm + lr * SROW + lc)       = make_float2(acc[mf][nf][0], acc[mf][nf][1]);
            *(float2*)(sm + (lr + 8) * SROW + lc) = make_float2(acc[mf][nf][2], acc[mf][nf][3]);
        }
    }
    __syncthreads();

    const int pblk = bcol >> 7;
#pragma unroll
    for (int it = 0; it < 16; it++) {
        int idx = it * 256 + tid;
        int r  = idx >> 5;
        int c0 = (idx & 31) * 2;
        int srow = (brow + r) & (SEQ - 1);
        int j0 = 64 * pblk + c0;
        float4 t0 = g_tab[(srow << 9) | j0];
        float4 t1 = g_tab[(srow << 9) | (j0 + 1)];
        float x1a = sm[r * SROW + c0]      + bias[j0];
        float x1b = sm[r * SROW + c0 + 1]  + bias[j0 + 1];
        float x2a = sm[r * SROW + c0 + 64] + bias[j0 + 512];
        float x2b = sm[r * SROW + c0 + 65] + bias[j0 + 513];
        float y1a = (x1a * t0.x + x2a * t0.y) * scale;
        float y2a = (x2a * t0.z - x1a * t0.w) * scale;
        float y1b = (x1b * t1.x + x2b * t1.y) * scale;
        float y2b = (x2b * t1.z - x1b * t1.w) * scale;
        size_t gb = (size_t)(brow + r) * HID + bcol;
        uint32_t hi, lo;
        split2(y1a, y1b, hi, lo);
        *(uint32_t*)(outh + gb + c0) = hi;
        *(uint32_t*)(outl + gb + c0) = lo;
        split2(y2a, y2b, hi, lo);
        *(uint32_t*)(outh + gb + 64 + c0) = hi;
        *(uint32_t*)(outl + gb + 64 + c0) = lo;
    }
}

// ============================================================================
// tensor-core flash attention with double-buffered cp.async K/V stages.
// ============================================================================
#define AST 144
#define AQ_H 0
#define AQ_L (128 * AST)              // 18432
#define AKV0 (2 * 128 * AST)          // 36864
#define KVSTG (4 * 64 * AST)          // 36864
#define ATTN_SMEM (AKV0 + 2 * KVSTG)  // 110592

__device__ __forceinline__ void attn_issue_kv(
    int krow0, size_t colbase, uint32_t kvbase, int tid)
{
#pragma unroll
    for (int i = 0; i < 8; i++) {
        const __nv_bfloat16* g = (i < 2) ? g_Kh : (i < 4) ? g_Kl
                               : (i < 6) ? g_Vh : g_Vl;
        const int arr = i >> 1;
        const int rem = ((i & 1) << 8) + tid;
        const int row = rem >> 3;
        const int c = rem & 7;
        cp16(kvbase + arr * (64 * AST) + row * AST + c * 16,
             g + (size_t)(krow0 + row) * HID + colbase + c * 8);
    }
}

__global__ __launch_bounds__(256, 2) void attn_mma() {
    extern __shared__ __align__(128) char smem[];

    const int tid  = threadIdx.x;
    const int wid  = tid >> 5;
    const int lane = tid & 31;
    const int qt   = blockIdx.x;
    const int bh   = blockIdx.y;
    const int b    = bh >> 4;
    const int h    = bh & 15;
    const int qbase = b * SEQ + qt * 128;
    const size_t colbase = (size_t)h * HD;
    const int krow_base = b * SEQ;

    const uint32_t sb = smem_u32(smem);

    const uint32_t aoff = (uint32_t)(((lane & 7) + ((lane >> 3) & 1) * 8) * AST
                                     + ((lane >> 4) & 1) * 16);
    const uint32_t boff = (uint32_t)(((lane & 7) + ((lane >> 4) & 1) * 8) * AST
                                     + ((lane >> 3) & 1) * 16);
    const uint32_t voff = (uint32_t)(((lane & 7) + ((lane >> 3) & 1) * 8) * AST
                                     + ((lane >> 4) & 1) * 16);

    // group 0: Q (both splits) + KV stage 0
#pragma unroll
    for (int i = 0; i < 8; i++) {
        const __nv_bfloat16* g = (i < 4) ? g_Qh : g_Ql;
        const int t = i >> 2;
        const int rem = ((i & 3) << 8) + tid;
        const int row = rem >> 3;
        const int c = rem & 7;
        cp16(sb + t * (128 * AST) + row * AST + c * 16,
             g + (size_t)(qbase + row) * HID + colbase + c * 8);
    }
    attn_issue_kv(krow_base, colbase, sb + AKV0, tid);
    CP_COMMIT();
    attn_issue_kv(krow_base + 64, colbase, sb + AKV0 + KVSTG, tid);
    CP_COMMIT();

    float o[8][4];
#pragma unroll
    for (int nf = 0; nf < 8; nf++)
#pragma unroll
        for (int r = 0; r < 4; r++) o[nf][r] = 0.0f;
    float m0 = -1e30f, m1 = -1e30f, l0 = 0.0f, l1 = 0.0f;

    const uint32_t qrow_off = (uint32_t)(wid * 16 * AST);

    for (int kt = 0; kt < 16; kt++) {
        const int s = kt & 1;
        CP_WAIT1();
        __syncthreads();

        const uint32_t kvb = sb + AKV0 + s * KVSTG;
        const uint32_t akh = kvb;
        const uint32_t akl = kvb + 64 * AST;
        const uint32_t avh = kvb + 2 * 64 * AST;
        const uint32_t avl = kvb + 3 * 64 * AST;

        float sfr[8][4];
#pragma unroll
        for (int nf = 0; nf < 8; nf++)
#pragma unroll
            for (int r = 0; r < 4; r++) sfr[nf][r] = 0.0f;

#pragma unroll
        for (int kq = 0; kq < 4; kq++) {
            uint32_t qh[4], ql[4];
            ldm4(qh, sb + AQ_H + qrow_off + kq * 32 + aoff);
            ldm4(ql, sb + AQ_L + qrow_off + kq * 32 + aoff);
            uint32_t kh[4][4], kl[4][4];
#pragma unroll
            for (int p = 0; p < 4; p++) {
                ldm4(kh[p], akh + (uint32_t)(p * 16 * AST) + kq * 32 + boff);
                ldm4(kl[p], akl + (uint32_t)(p * 16 * AST) + kq * 32 + boff);
            }
#pragma unroll
            for (int nf = 0; nf < 8; nf++) {
                const int p = nf >> 1, q = nf & 1;
                mma16816(sfr[nf], qh, kh[p][2 * q], kh[p][2 * q + 1]);
                mma16816(sfr[nf], qh, kl[p][2 * q], kl[p][2 * q + 1]);
                mma16816(sfr[nf], ql, kh[p][2 * q], kh[p][2 * q + 1]);
            }
        }

        float mx0 = -1e30f, mx1 = -1e30f;
#pragma unroll
        for (int nf = 0; nf < 8; nf++) {
            mx0 = fmaxf(mx0, fmaxf(sfr[nf][0], sfr[nf][1]));
            mx1 = fmaxf(mx1, fmaxf(sfr[nf][2], sfr[nf][3]));
        }
        mx0 = fmaxf(mx0, __shfl_xor_sync(0xFFFFFFFF, mx0, 1));
        mx0 = fmaxf(mx0, __shfl_xor_sync(0xFFFFFFFF, mx0, 2));
        mx1 = fmaxf(mx1, __shfl_xor_sync(0xFFFFFFFF, mx1, 1));
        mx1 = fmaxf(mx1, __shfl_xor_sync(0xFFFFFFFF, mx1, 2));

        float mn0 = fmaxf(m0, mx0), mn1 = fmaxf(m1, mx1);
        float c0 = __expf(m0 - mn0), c1 = __expf(m1 - mn1);
        l0 *= c0; l1 *= c1;
#pragma unroll
        for (int nf = 0; nf < 8; nf++) {
            o[nf][0] *= c0; o[nf][1] *= c0;
            o[nf][2] *= c1; o[nf][3] *= c1;
        }
#pragma unroll
        for (int nf = 0; nf < 8; nf++) {
            sfr[nf][0] = __expf(sfr[nf][0] - mn0);
            sfr[nf][1] = __expf(sfr[nf][1] - mn0);
            sfr[nf][2] = __expf(sfr[nf][2] - mn1);
            sfr[nf][3] = __expf(sfr[nf][3] - mn1);
            l0 += sfr[nf][0] + sfr[nf][1];
            l1 += sfr[nf][2] + sfr[nf][3];
        }
        m0 = mn0; m1 = mn1;

#pragma unroll
        for (int kk = 0; kk < 4; kk++) {
            uint32_t ah[4], al[4];
            split2(sfr[2 * kk][0],     sfr[2 * kk][1],     ah[0], al[0]);
            split2(sfr[2 * kk][2],     sfr[2 * kk][3],     ah[1], al[1]);
            split2(sfr[2 * kk + 1][0], sfr[2 * kk + 1][1], ah[2], al[2]);
            split2(sfr[2 * kk + 1][2], sfr[2 * kk + 1][3], ah[3], al[3]);

            uint32_t vh[4][4], vl[4][4];
#pragma unroll
            for (int p = 0; p < 4; p++) {
                uint32_t ro = (uint32_t)(kk * 16 * AST) + (uint32_t)(p * 32);
                ldm4t(vh[p], avh + ro + voff);
                ldm4t(vl[p], avl + ro + voff);
            }
#pragma unroll
            for (int nf = 0; nf < 8; nf++) {
                const int p = nf >> 1, q = nf & 1;
                mma16816(o[nf], ah, vh[p][2 * q], vh[p][2 * q + 1]);
                mma16816(o[nf], ah, vl[p][2 * q], vl[p][2 * q + 1]);
                mma16816(o[nf], al, vh[p][2 * q], vh[p][2 * q + 1]);
            }
        }

        __syncthreads();
        if (kt + 2 < 16)
            attn_issue_kv(krow_base + (kt + 2) * 64, colbase,
                          sb + AKV0 + s * KVSTG, tid);
        CP_COMMIT();
    }

    l0 += __shfl_xor_sync(0xFFFFFFFF, l0, 1);
    l0 += __shfl_xor_sync(0xFFFFFFFF, l0, 2);
    l1 += __shfl_xor_sync(0xFFFFFFFF, l1, 1);
    l1 += __shfl_xor_sync(0xFFFFFFFF, l1, 2);
    float inv0 = 1.0f / l0, inv1 = 1.0f / l1;

    const int g  = lane >> 2;
    const int t2 = (lane & 3) * 2;
    const int row0 = qbase + wid * 16 + g;
#pragma unroll
    for (int nf = 0; nf < 8; nf++) {
        size_t col = colbase + nf * 8 + t2;
        uint32_t hi, lo;
        split2(o[nf][0] * inv0, o[nf][1] * inv0, hi, lo);
        *(uint32_t*)(g_Ahi + (size_t)row0 * HID + col) = hi;
        *(uint32_t*)(g_Alo + (size_t)row0 * HID + col) = lo;
        split2(o[nf][2] * inv1, o[nf][3] * inv1, hi, lo);
        *(uint32_t*)(g_Ahi + (size_t)(row0 + 8) * HID + col) = hi;
        *(uint32_t*)(g_Alo + (size_t)(row0 + 8) * HID + col) = lo;
    }
}

// ============================================================================
// launch
// ============================================================================
extern "C" void kernel_launch(void* const* d_in, const int* in_sizes, int n_in,
                              void* d_out, int out_size) {
    (void)in_sizes; (void)n_in; (void)out_size;
    const float* query = (const float*)d_in[0];
    const float* key   = (const float*)d_in[1];
    const float* value = (const float*)d_in[2];
    const float* Wq    = (const float*)d_in[3];
    const float* bq    = (const float*)d_in[4];
    const float* Wk    = (const float*)d_in[5];
    const float* bk    = (const float*)d_in[6];
    const float* Wv    = (const float*)d_in[7];
    const float* bv    = (const float*)d_in[8];
    const float* Wo    = (const float*)d_in[9];
    const float* bo    = (const float*)d_in[10];
    float* out = (float*)d_out;

    __nv_bfloat16 *Qh, *Ql, *Kh, *Kl, *Vh, *Vl, *Ahi, *Alo;
    __nv_bfloat16 *Wqh, *Wql, *Wkh, *Wkl, *Wvh, *Wvl, *Woh, *Wol;
    cudaGetSymbolAddress((void**)&Qh, g_Qh);   cudaGetSymbolAddress((void**)&Ql, g_Ql);
    cudaGetSymbolAddress((void**)&Kh, g_Kh);   cudaGetSymbolAddress((void**)&Kl, g_Kl);
    cudaGetSymbolAddress((void**)&Vh, g_Vh);   cudaGetSymbolAddress((void**)&Vl, g_Vl);
    cudaGetSymbolAddress((void**)&Ahi, g_Ahi); cudaGetSymbolAddress((void**)&Alo, g_Alo);
    cudaGetSymbolAddress((void**)&Wqh, g_Wqh); cudaGetSymbolAddress((void**)&Wql, g_Wql);
    cudaGetSymbolAddress((void**)&Wkh, g_Wkh); cudaGetSymbolAddress((void**)&Wkl, g_Wkl);
    cudaGetSymbolAddress((void**)&Wvh, g_Wvh); cudaGetSymbolAddress((void**)&Wvl, g_Wvl);
    cudaGetSymbolAddress((void**)&Woh, g_Woh); cudaGetSymbolAddress((void**)&Wol, g_Wol);

    cudaFuncSetAttribute(gemm_pipe<true>,  cudaFuncAttributeMaxDynamicSharedMemorySize, GEMM_SMEM);
    cudaFuncSetAttribute(gemm_pipe<false>, cudaFuncAttributeMaxDynamicSharedMemorySize, GEMM_SMEM);
    cudaFuncSetAttribute(attn_mma, cudaFuncAttributeMaxDynamicSharedMemorySize, ATTN_SMEM);

    dim3 ggrid(HID / 128, MROWS / 128);
    const int wblocks = (HID * HID / 8) / 256;      // 512
    const int ablocks = (MROWS * HID / 8) / 256;    // 4096

    make_invf_kernel<<<1, 512>>>();
    rope_table_kernel<<<(SEQ * 512) / 256, 256>>>();

    prep_w_rowperm<<<wblocks, 256>>>(Wq, Wqh, Wql);
    prep_w_rowperm<<<wblocks, 256>>>(Wk, Wkh, Wkl);
    prep_w_rowperm<<<wblocks, 256>>>(Wv, Wvh, Wvl);
    prep_w_colperm<<<wblocks, 256>>>(Wo, Woh, Wol);

    // Q projection (A split staged through g_Ahi/g_Alo scratch)
    split_act_kernel<<<ablocks, 256>>>(query, Ahi, Alo);
    gemm_pipe<true><<<ggrid, 256, GEMM_SMEM>>>(Ahi, Alo, Wqh, Wql, bq, Qh, Ql, nullptr, 0.125f);
    split_act_kernel<<<ablocks, 256>>>(key, Ahi, Alo);
    gemm_pipe<true><<<ggrid, 256, GEMM_SMEM>>>(Ahi, Alo, Wkh, Wkl, bk, Kh, Kl, nullptr, 1.0f);
    split_act_kernel<<<ablocks, 256>>>(value, Ahi, Alo);
    gemm_pipe<true><<<ggrid, 256, GEMM_SMEM>>>(Ahi, Alo, Wvh, Wvl, bv, Vh, Vl, nullptr, 1.0f);

    attn_mma<<<dim3(8, 128), 256, ATTN_SMEM>>>();

    gemm_pipe<false><<<ggrid, 256, GEMM_SMEM>>>(Ahi, Alo, Woh, Wol, bo, nullptr, nullptr, out, 1.0f);
}

// round 8
// speedup vs baseline: 1.6555x; 1.6555x over previous
#include <cuda_runtime.h>
#include <cuda_fp16.h>
#include <cstdint>

#define HID 1024
#define HEADS 16
#define HD 64
#define BATCH 8
#define SEQ 1024
#define MROWS (BATCH * SEQ)

// ---------------- scratch (device globals; no allocation allowed) ----------
__device__ __half g_Qh[MROWS * HID];
__device__ __half g_Ql[MROWS * HID];
__device__ __half g_Kh[MROWS * HID];
__device__ __half g_Vh[MROWS * HID];
__device__ __half g_Ahi[MROWS * HID];
__device__ __half g_Alo[MROWS * HID];
__device__ __half g_Wqh[HID * HID];
__device__ __half g_Wkh[HID * HID];
__device__ __half g_Wvh[HID * HID];
__device__ __half g_Woh[HID * HID];
__device__ float g_invf[HID / 2];
__device__ float4 g_tab[SEQ * (HID / 2)];

// ---------------- helpers ----------------------------------------
__device__ __forceinline__ uint32_t smem_u32(const void* p) {
    uint32_t a;
    asm("{ .reg .u64 t; cvta.to.shared.u64 t, %1; cvt.u32.u64 %0, t; }"
        : "=r"(a) : "l"(p));
    return a;
}
__device__ __forceinline__ void cp16(uint32_t dst, const void* src) {
    asm volatile("cp.async.cg.shared.global [%0], [%1], 16;" :: "r"(dst), "l"(src));
}
#define CP_COMMIT() asm volatile("cp.async.commit_group;" ::: "memory")
#define CP_WAIT1()  asm volatile("cp.async.wait_group 1;" ::: "memory")

__device__ __forceinline__ void ldm4(uint32_t* r, uint32_t addr) {
    asm volatile("ldmatrix.sync.aligned.m8n8.x4.shared.b16 {%0,%1,%2,%3}, [%4];"
                 : "=r"(r[0]), "=r"(r[1]), "=r"(r[2]), "=r"(r[3]) : "r"(addr));
}
__device__ __forceinline__ void ldm4t(uint32_t* r, uint32_t addr) {
    asm volatile("ldmatrix.sync.aligned.m8n8.x4.trans.shared.b16 {%0,%1,%2,%3}, [%4];"
                 : "=r"(r[0]), "=r"(r[1]), "=r"(r[2]), "=r"(r[3]) : "r"(addr));
}
__device__ __forceinline__ void mma16816(float* d, const uint32_t* a,
                                         uint32_t b0, uint32_t b1) {
    asm volatile(
        "mma.sync.aligned.m16n8k16.row.col.f32.f16.f16.f32 "
        "{%0,%1,%2,%3}, {%4,%5,%6,%7}, {%8,%9}, {%0,%1,%2,%3};"
        : "+f"(d[0]), "+f"(d[1]), "+f"(d[2]), "+f"(d[3])
        : "r"(a[0]), "r"(a[1]), "r"(a[2]), "r"(a[3]), "r"(b0), "r"(b1));
}
// fp16 split: pair of floats -> half2 hi + half2 lo (packed u32)
__device__ __forceinline__ void split2h(float x, float y, uint32_t& hi, uint32_t& lo) {
    __half2 h = __floats2half2_rn(x, y);
    float2 f = __half22float2(h);
    __half2 l2 = __floats2half2_rn(x - f.x, y - f.y);
    hi = *reinterpret_cast<uint32_t*>(&h);
    lo = *reinterpret_cast<uint32_t*>(&l2);
}
__device__ __forceinline__ void split8h(const float4& u, const float4& v,
                                        uint4& hi, uint4& lo) {
    split2h(u.x, u.y, hi.x, lo.x);
    split2h(u.z, u.w, hi.y, lo.y);
    split2h(v.x, v.y, hi.z, lo.z);
    split2h(v.z, v.w, hi.w, lo.w);
}
// permutation: n' = 128p + 64s + i  ->  orig = 64p + 512s + i
__device__ __forceinline__ int perm_orig(int n) {
    int p = n >> 7, s = (n >> 6) & 1, i = n & 63;
    return 64 * p + 512 * s + i;
}

// ============================================================================
// weight prep: single fp16 (rn-rounded), row-permuted / col-permuted
// ============================================================================
__global__ __launch_bounds__(256) void prep_w_rowperm(
    const float* __restrict__ W, __half* __restrict__ Wh)
{
    int idx = blockIdx.x * 256 + threadIdx.x;   // HID*HID/8
    int n = idx >> 7;
    int c8 = (idx & 127) * 8;
    int orig = perm_orig(n);
    float4 u = *(const float4*)(W + (size_t)orig * HID + c8);
    float4 v = *(const float4*)(W + (size_t)orig * HID + c8 + 4);
    __half2 h0 = __floats2half2_rn(u.x, u.y);
    __half2 h1 = __floats2half2_rn(u.z, u.w);
    __half2 h2 = __floats2half2_rn(v.x, v.y);
    __half2 h3 = __floats2half2_rn(v.z, v.w);
    uint4 o = make_uint4(*(uint32_t*)&h0, *(uint32_t*)&h1, *(uint32_t*)&h2, *(uint32_t*)&h3);
    *(uint4*)(Wh + (size_t)n * HID + c8) = o;
}

__global__ __launch_bounds__(256) void prep_w_colperm(
    const float* __restrict__ W, __half* __restrict__ Wh)
{
    int idx = blockIdx.x * 256 + threadIdx.x;
    int n = idx >> 7;
    int k8 = (idx & 127) * 8;
    int orig = perm_orig(k8);
    float4 u = *(const float4*)(W + (size_t)n * HID + orig);
    float4 v = *(const float4*)(W + (size_t)n * HID + orig + 4);
    __half2 h0 = __floats2half2_rn(u.x, u.y);
    __half2 h1 = __floats2half2_rn(u.z, u.w);
    __half2 h2 = __floats2half2_rn(v.x, v.y);
    __half2 h3 = __floats2half2_rn(v.z, v.w);
    uint4 o = make_uint4(*(uint32_t*)&h0, *(uint32_t*)&h1, *(uint32_t*)&h2, *(uint32_t*)&h3);
    *(uint4*)(Wh + (size_t)n * HID + k8) = o;
}

__global__ void make_invf_kernel() {
    int j = threadIdx.x;
    if (j < HID / 2) {
        double e = exp(-((double)(2 * j) / (double)HID) * log(10000.0));
        g_invf[j] = (float)e;
    }
}
__global__ __launch_bounds__(256) void rope_table_kernel() {
    int idx = blockIdx.x * 256 + threadIdx.x;
    int s = idx >> 9;
    int j = idx & 511;
    float t = (float)s * g_invf[j];
    float st, ct;
    sincosf(t, &st, &ct);
    float s1, c1, s2, c2;
    sincosf(st, &s1, &c1);
    sincosf(ct, &s2, &c2);
    g_tab[idx] = make_float4(c1, s1, c2, s2);
}

// ============================================================================
// fused QKV projection: Y = X*W'^T (+bias +RoPE +scale) -> fp16 hi(/lo).
// A = fp32 converted inline to fp16 hi/lo; B = single fp16 weights.
// 2-term MMA: ah*b + al*b. CTA 128x128, warp 64x32, K-chunk 32, 2-stage.
// ============================================================================
#define RSTRIDE 80
#define TILE_B (128 * RSTRIDE)      // 10240
#define STAGE_B (3 * TILE_B)        // 30720 (Ah, Al, B)
#define GEMM_SMEM 67584             // max(2*STAGE_B=61440, 128*132*4=67584)
#define SROW 132

template <bool WANT_LO>
__global__ __launch_bounds__(256)
void gemm_qkv(const float* __restrict__ X, const __half* __restrict__ Bw,
              const float* __restrict__ bias,
              __half* __restrict__ outh, __half* __restrict__ outl, float scale)
{
    extern __shared__ __align__(128) char smem[];

    const int tid  = threadIdx.x;
    const int wid  = tid >> 5;
    const int lane = tid & 31;
    const int wm   = wid & 1;
    const int wn   = wid >> 1;
    const int brow = blockIdx.y * 128;
    const int bcol = blockIdx.x * 128;

    const uint32_t sbase = smem_u32(smem);
    const uint32_t aoff = (uint32_t)(((lane & 7) + ((lane >> 3) & 1) * 8) * RSTRIDE
                                     + ((lane >> 4) & 1) * 16);
    const uint32_t boff = (uint32_t)(((lane & 7) + ((lane >> 4) & 1) * 8) * RSTRIDE
                                     + ((lane >> 3) & 1) * 16);

    // load mapping: 128 rows x 4 chunks(16B) per tile; 2 iters/thread
    const int r0i = tid >> 2;          // rows r0i, r0i+64
    const int ch  = tid & 3;

    const float* Xp = X + (size_t)brow * HID;
    const __half* Bp = Bw + (size_t)bcol * HID;

    float acc[4][4][4];
#pragma unroll
    for (int i = 0; i < 4; i++)
#pragma unroll
        for (int j = 0; j < 4; j++)
#pragma unroll
            for (int r = 0; r < 4; r++) acc[i][j][r] = 0.0f;

    // prologue: chunk 0 -> stage 0
    {
        const size_t ke = (size_t)ch * 8;
        float4 a0 = *(const float4*)(Xp + (size_t)r0i * HID + ke);
        float4 a1 = *(const float4*)(Xp + (size_t)r0i * HID + ke + 4);
        float4 a2 = *(const float4*)(Xp + (size_t)(r0i + 64) * HID + ke);
        float4 a3 = *(const float4*)(Xp + (size_t)(r0i + 64) * HID + ke + 4);
        uint4 b0 = *(const uint4*)(Bp + (size_t)r0i * HID + ke);
        uint4 b1 = *(const uint4*)(Bp + (size_t)(r0i + 64) * HID + ke);
        uint4 hi, lo;
        split8h(a0, a1, hi, lo);
        *(uint4*)(smem + 0 * TILE_B + r0i * RSTRIDE + ch * 16) = hi;
        *(uint4*)(smem + 1 * TILE_B + r0i * RSTRIDE + ch * 16) = lo;
        split8h(a2, a3, hi, lo);
        *(uint4*)(smem + 0 * TILE_B + (r0i + 64) * RSTRIDE + ch * 16) = hi;
        *(uint4*)(smem + 1 * TILE_B + (r0i + 64) * RSTRIDE + ch * 16) = lo;
        *(uint4*)(smem + 2 * TILE_B + r0i * RSTRIDE + ch * 16) = b0;
        *(uint4*)(smem + 2 * TILE_B + (r0i + 64) * RSTRIDE + ch * 16) = b1;
    }
    __syncthreads();

    for (int kc = 0; kc < 32; kc++) {
        const int s = kc & 1;
        const bool has = (kc + 1) < 32;

        float4 pa[4];
        uint4 pb[2];
        if (has) {
            const size_t ke = (size_t)(kc + 1) * 32 + (size_t)ch * 8;
            pa[0] = *(const float4*)(Xp + (size_t)r0i * HID + ke);
            pa[1] = *(const float4*)(Xp + (size_t)r0i * HID + ke + 4);
            pa[2] = *(const float4*)(Xp + (size_t)(r0i + 64) * HID + ke);
            pa[3] = *(const float4*)(Xp + (size_t)(r0i + 64) * HID + ke + 4);
            pb[0] = *(const uint4*)(Bp + (size_t)r0i * HID + ke);
            pb[1] = *(const uint4*)(Bp + (size_t)(r0i + 64) * HID + ke);
        }

        const uint32_t base = sbase + s * STAGE_B;
#pragma unroll
        for (int ks = 0; ks < 2; ks++) {
            const uint32_t kb = ks * 32;
            uint32_t ah[4][4], al[4][4];
#pragma unroll
            for (int mf = 0; mf < 4; mf++) {
                uint32_t ro = (uint32_t)((wm * 64 + mf * 16) * RSTRIDE) + kb;
                ldm4(ah[mf], base + ro + aoff);
                ldm4(al[mf], base + TILE_B + ro + aoff);
            }
            uint32_t bh[2][4];
#pragma unroll
            for (int p = 0; p < 2; p++) {
                uint32_t ro = (uint32_t)((wn * 32 + p * 16) * RSTRIDE) + kb;
                ldm4(bh[p], base + 2 * TILE_B + ro + boff);
            }
#pragma unroll
            for (int mf = 0; mf < 4; mf++) {
#pragma unroll
                for (int nf = 0; nf < 4; nf++) {
                    const int p = nf >> 1, q = nf & 1;
                    mma16816(acc[mf][nf], ah[mf], bh[p][2 * q], bh[p][2 * q + 1]);
                    mma16816(acc[mf][nf], al[mf], bh[p][2 * q], bh[p][2 * q + 1]);
                }
            }
        }

        if (has) {
            char* st = smem + (s ^ 1) * STAGE_B;
            uint4 hi, lo;
            split8h(pa[0], pa[1], hi, lo);
            *(uint4*)(st + 0 * TILE_B + r0i * RSTRIDE + ch * 16) = hi;
            *(uint4*)(st + 1 * TILE_B + r0i * RSTRIDE + ch * 16) = lo;
            split8h(pa[2], pa[3], hi, lo);
            *(uint4*)(st + 0 * TILE_B + (r0i + 64) * RSTRIDE + ch * 16) = hi;
            *(uint4*)(st + 1 * TILE_B + (r0i + 64) * RSTRIDE + ch * 16) = lo;
            *(uint4*)(st + 2 * TILE_B + r0i * RSTRIDE + ch * 16) = pb[0];
            *(uint4*)(st + 2 * TILE_B + (r0i + 64) * RSTRIDE + ch * 16) = pb[1];
        }
        __syncthreads();
    }

    // epilogue: stage fp32 tile, apply bias + RoPE + scale, write fp16 hi(/lo)
    float* sm = (float*)smem;
    const int g  = lane >> 2;
    const int t2 = (lane & 3) * 2;
#pragma unroll
    for (int mf = 0; mf < 4; mf++) {
        const int lr = wm * 64 + mf * 16 + g;
#pragma unroll
        for (int nf = 0; nf < 4; nf++) {
            const int lc = wn * 32 + nf * 8 + t2;
            *(float2*)(sm + lr * SROW + lc)       = make_float2(acc[mf][nf][0], acc[mf][nf][1]);
            *(float2*)(sm + (lr + 8) * SROW + lc) = make_float2(acc[mf][nf][2], acc[mf][nf][3]);
        }
    }
    __syncthreads();

    const int pblk = bcol >> 7;
#pragma unroll
    for (int it = 0; it < 16; it++) {
        int idx = it * 256 + tid;
        int r  = idx >> 5;
        int c0 = (idx & 31) * 2;
        int srow = (brow + r) & (SEQ - 1);
        int j0 = 64 * pblk + c0;
        float4 t0 = g_tab[(srow << 9) | j0];
        float4 t1 = g_tab[(srow << 9) | (j0 + 1)];
        float x1a = sm[r * SROW + c0]      + bias[j0];
        float x1b = sm[r * SROW + c0 + 1]  + bias[j0 + 1];
        float x2a = sm[r * SROW + c0 + 64] + bias[j0 + 512];
        float x2b = sm[r * SROW + c0 + 65] + bias[j0 + 513];
        float y1a = (x1a * t0.x + x2a * t0.y) * scale;
        float y2a = (x2a * t0.z - x1a * t0.w) * scale;
        float y1b = (x1b * t1.x + x2b * t1.y) * scale;
        float y2b = (x2b * t1.z - x1b * t1.w) * scale;
        size_t gb = (size_t)(brow + r) * HID + bcol;
        uint32_t hi, lo;
        split2h(y1a, y1b, hi, lo);
        *(uint32_t*)(outh + gb + c0) = hi;
        if (WANT_LO) *(uint32_t*)(outl + gb + c0) = lo;
        split2h(y2a, y2b, hi, lo);
        *(uint32_t*)(outh + gb + 64 + c0) = hi;
        if (WANT_LO) *(uint32_t*)(outl + gb + 64 + c0) = lo;
    }
}

// ============================================================================
// output projection: out = Ctx*Wo'^T + bo (fp32). Ctx = fp16 hi/lo splits.
// ============================================================================
__global__ __launch_bounds__(256)
void gemm_out(const __half* __restrict__ Ahi, const __half* __restrict__ Alo,
              const __half* __restrict__ Bw,
              const float* __restrict__ bias, float* __restrict__ Y)
{
    extern __shared__ __align__(128) char smem[];

    const int tid  = threadIdx.x;
    const int wid  = tid >> 5;
    const int lane = tid & 31;
    const int wm   = wid & 1;
    const int wn   = wid >> 1;
    const int brow = blockIdx.y * 128;
    const int bcol = blockIdx.x * 128;

    const uint32_t sbase = smem_u32(smem);
    const uint32_t aoff = (uint32_t)(((lane & 7) + ((lane >> 3) & 1) * 8) * RSTRIDE
                                     + ((lane >> 4) & 1) * 16);
    const uint32_t boff = (uint32_t)(((lane & 7) + ((lane >> 4) & 1) * 8) * RSTRIDE
                                     + ((lane >> 3) & 1) * 16);

    const int r0i = tid >> 2;
    const int ch  = tid & 3;

    const __half* gptr[3];
    gptr[0] = Ahi + (size_t)brow * HID;
    gptr[1] = Alo + (size_t)brow * HID;
    gptr[2] = Bw  + (size_t)bcol * HID;

    float acc[4][4][4];
#pragma unroll
    for (int i = 0; i < 4; i++)
#pragma unroll
        for (int j = 0; j < 4; j++)
#pragma unroll
            for (int r = 0; r < 4; r++) acc[i][j][r] = 0.0f;

    {
        const size_t ke = (size_t)ch * 8;
#pragma unroll
        for (int t = 0; t < 3; t++) {
            uint4 v0 = *(const uint4*)(gptr[t] + (size_t)r0i * HID + ke);
            uint4 v1 = *(const uint4*)(gptr[t] + (size_t)(r0i + 64) * HID + ke);
            *(uint4*)(smem + t * TILE_B + r0i * RSTRIDE + ch * 16) = v0;
            *(uint4*)(smem + t * TILE_B + (r0i + 64) * RSTRIDE + ch * 16) = v1;
        }
    }
    __syncthreads();

    for (int kc = 0; kc < 32; kc++) {
        const int s = kc & 1;
        const bool has = (kc + 1) < 32;

        uint4 pf[3][2];
        if (has) {
            const size_t ke = (size_t)(kc + 1) * 32 + (size_t)ch * 8;
#pragma unroll
            for (int t = 0; t < 3; t++) {
                pf[t][0] = *(const uint4*)(gptr[t] + (size_t)r0i * HID + ke);
                pf[t][1] = *(const uint4*)(gptr[t] + (size_t)(r0i + 64) * HID + ke);
            }
        }

        const uint32_t base = sbase + s * STAGE_B;
#pragma unroll
        for (int ks = 0; ks < 2; ks++) {
            const uint32_t kb = ks * 32;
            uint32_t ah[4][4], al[4][4];
#pragma unroll
            for (int mf = 0; mf < 4; mf++) {
                uint32_t ro = (uint32_t)((wm * 64 + mf * 16) * RSTRIDE) + kb;
                ldm4(ah[mf], base + ro + aoff);
                ldm4(al[mf], base + TILE_B + ro + aoff);
            }
            uint32_t bh[2][4];
#pragma unroll
            for (int p = 0; p < 2; p++) {
                uint32_t ro = (uint32_t)((wn * 32 + p * 16) * RSTRIDE) + kb;
                ldm4(bh[p], base + 2 * TILE_B + ro + boff);
            }
#pragma unroll
            for (int mf = 0; mf < 4; mf++) {
#pragma unroll
                for (int nf = 0; nf < 4; nf++) {
                    const int p = nf >> 1, q = nf & 1;
                    mma16816(acc[mf][nf], ah[mf], bh[p][2 * q], bh[p][2 * q + 1]);
                    mma16816(acc[mf][nf], al[mf], bh[p][2 * q], bh[p][2 * q + 1]);
                }
            }
        }

        if (has) {
            char* st = smem + (s ^ 1) * STAGE_B;
#pragma unroll
            for (int t = 0; t < 3; t++) {
                *(uint4*)(st + t * TILE_B + r0i * RSTRIDE + ch * 16) = pf[t][0];
                *(uint4*)(st + t * TILE_B + (r0i + 64) * RSTRIDE + ch * 16) = pf[t][1];
            }
        }
        __syncthreads();
    }

    const int g = lane >> 2;
    const int t2 = (lane & 3) * 2;
#pragma unroll
    for (int mf = 0; mf < 4; mf++) {
        const int row0 = brow + wm * 64 + mf * 16 + g;
#pragma unroll
        for (int nf = 0; nf < 4; nf++) {
            const int col = bcol + wn * 32 + nf * 8 + t2;
            float2 bv = *(const float2*)(bias + col);
            *(float2*)(Y + (size_t)row0 * HID + col) =
                make_float2(acc[mf][nf][0] + bv.x, acc[mf][nf][1] + bv.y);
            *(float2*)(Y + (size_t)(row0 + 8) * HID + col) =
                make_float2(acc[mf][nf][2] + bv.x, acc[mf][nf][3] + bv.y);
        }
    }
}

// ============================================================================
// tensor-core flash attention, fp16 2-term. Q split hi/lo; K,V single fp16.
// cp.async double-buffered K/V stages. Ctx written as fp16 hi/lo splits.
// ============================================================================
#define AST 144
#define AQ_H 0
#define AQ_L (128 * AST)              // 18432
#define AKV0 (2 * 128 * AST)          // 36864
#define KVSTG (2 * 64 * AST)          // 18432 (K, V)
#define ATTN_SMEM (AKV0 + 2 * KVSTG)  // 73728

__device__ __forceinline__ void attn_issue_kv(
    int krow0, size_t colbase, uint32_t kvbase, int tid)
{
#pragma unroll
    for (int i = 0; i < 4; i++) {
        const __half* g = (i < 2) ? g_Kh : g_Vh;
        const int arr = i >> 1;
        const int rem = ((i & 1) << 8) + tid;
        const int row = rem >> 3;
        const int c = rem & 7;
        cp16(kvbase + arr * (64 * AST) + row * AST + c * 16,
             g + (size_t)(krow0 + row) * HID + colbase + c * 8);
    }
}

__global__ __launch_bounds__(256, 2) void attn_mma() {
    extern __shared__ __align__(128) char smem[];

    const int tid  = threadIdx.x;
    const int wid  = tid >> 5;
    const int lane = tid & 31;
    const int qt   = blockIdx.x;
    const int bh   = blockIdx.y;
    const int b    = bh >> 4;
    const int h    = bh & 15;
    const int qbase = b * SEQ + qt * 128;
    const size_t colbase = (size_t)h * HD;
    const int krow_base = b * SEQ;

    const uint32_t sb = smem_u32(smem);

    const uint32_t aoff = (uint32_t)(((lane & 7) + ((lane >> 3) & 1) * 8) * AST
                                     + ((lane >> 4) & 1) * 16);
    const uint32_t boff = (uint32_t)(((lane & 7) + ((lane >> 4) & 1) * 8) * AST
                                     + ((lane >> 3) & 1) * 16);
    const uint32_t voff = (uint32_t)(((lane & 7) + ((lane >> 3) & 1) * 8) * AST
                                     + ((lane >> 4) & 1) * 16);

    // group 0: Q hi/lo + KV stage 0
#pragma unroll
    for (int i = 0; i < 8; i++) {
        const __half* g = (i < 4) ? g_Qh : g_Ql;
        const int t = i >> 2;
        const int rem = ((i & 3) << 8) + tid;
        const int row = rem >> 3;
        const int c = rem & 7;
        cp16(sb + t * (128 * AST) + row * AST + c * 16,
             g + (size_t)(qbase + row) * HID + colbase + c * 8);
    }
    attn_issue_kv(krow_base, colbase, sb + AKV0, tid);
    CP_COMMIT();
    attn_issue_kv(krow_base + 64, colbase, sb + AKV0 + KVSTG, tid);
    CP_COMMIT();

    float o[8][4];
#pragma unroll
    for (int nf = 0; nf < 8; nf++)
#pragma unroll
        for (int r = 0; r < 4; r++) o[nf][r] = 0.0f;
    float m0 = -1e30f, m1 = -1e30f, l0 = 0.0f, l1 = 0.0f;

    const uint32_t qrow_off = (uint32_t)(wid * 16 * AST);

    for (int kt = 0; kt < 16; kt++) {
        const int s = kt & 1;
        CP_WAIT1();
        __syncthreads();

        const uint32_t kvb = sb + AKV0 + s * KVSTG;
        const uint32_t akh = kvb;
        const uint32_t avh = kvb + 64 * AST;

        float sfr[8][4];
#pragma unroll
        for (int nf = 0; nf < 8; nf++)
#pragma unroll
            for (int r = 0; r < 4; r++) sfr[nf][r] = 0.0f;

#pragma unroll
        for (int kq = 0; kq < 4; kq++) {
            uint32_t qh[4], ql[4];
            ldm4(qh, sb + AQ_H + qrow_off + kq * 32 + aoff);
            ldm4(ql, sb + AQ_L + qrow_off + kq * 32 + aoff);
            uint32_t kh[4][4];
#pragma unroll
            for (int p = 0; p < 4; p++)
                ldm4(kh[p], akh + (uint32_t)(p * 16 * AST) + kq * 32 + boff);
#pragma unroll
            for (int nf = 0; nf < 8; nf++) {
                const int p = nf >> 1, q = nf & 1;
                mma16816(sfr[nf], qh, kh[p][2 * q], kh[p][2 * q + 1]);
                mma16816(sfr[nf], ql, kh[p][2 * q], kh[p][2 * q + 1]);
            }
        }

        float mx0 = -1e30f, mx1 = -1e30f;
#pragma unroll
        for (int nf = 0; nf < 8; nf++) {
            mx0 = fmaxf(mx0, fmaxf(sfr[nf][0], sfr[nf][1]));
            mx1 = fmaxf(mx1, fmaxf(sfr[nf][2], sfr[nf][3]));
        }
        mx0 = fmaxf(mx0, __shfl_xor_sync(0xFFFFFFFF, mx0, 1));
        mx0 = fmaxf(mx0, __shfl_xor_sync(0xFFFFFFFF, mx0, 2));
        mx1 = fmaxf(mx1, __shfl_xor_sync(0xFFFFFFFF, mx1, 1));
        mx1 = fmaxf(mx1, __shfl_xor_sync(0xFFFFFFFF, mx1, 2));

        float mn0 = fmaxf(m0, mx0), mn1 = fmaxf(m1, mx1);
        float c0 = __expf(m0 - mn0), c1 = __expf(m1 - mn1);
        l0 *= c0; l1 *= c1;
#pragma unroll
        for (int nf = 0; nf < 8; nf++) {
            o[nf][0] *= c0; o[nf][1] *= c0;
            o[nf][2] *= c1; o[nf][3] *= c1;
        }
#pragma unroll
        for (int nf = 0; nf < 8; nf++) {
            sfr[nf][0] = __expf(sfr[nf][0] - mn0);
            sfr[nf][1] = __expf(sfr[nf][1] - mn0);
            sfr[nf][2] = __expf(sfr[nf][2] - mn1);
            sfr[nf][3] = __expf(sfr[nf][3] - mn1);
            l0 += sfr[nf][0] + sfr[nf][1];
            l1 += sfr[nf][2] + sfr[nf][3];
        }
        m0 = mn0; m1 = mn1;

#pragma unroll
        for (int kk = 0; kk < 4; kk++) {
            uint32_t ah[4], al[4];
            split2h(sfr[2 * kk][0],     sfr[2 * kk][1],     ah[0], al[0]);
            split2h(sfr[2 * kk][2],     sfr[2 * kk][3],     ah[1], al[1]);
            split2h(sfr[2 * kk + 1][0], sfr[2 * kk + 1][1], ah[2], al[2]);
            split2h(sfr[2 * kk + 1][2], sfr[2 * kk + 1][3], ah[3], al[3]);

            uint32_t vh[4][4];
#pragma unroll
            for (int p = 0; p < 4; p++) {
                uint32_t ro = (uint32_t)(kk * 16 * AST) + (uint32_t)(p * 32);
                ldm4t(vh[p], avh + ro + voff);
            }
#pragma unroll
            for (int nf = 0; nf < 8; nf++) {
                const int p = nf >> 1, q = nf & 1;
                mma16816(o[nf], ah, vh[p][2 * q], vh[p][2 * q + 1]);
                mma16816(o[nf], al, vh[p][2 * q], vh[p][2 * q + 1]);
            }
        }

        __syncthreads();
        if (kt + 2 < 16)
            attn_issue_kv(krow_base + (kt + 2) * 64, colbase,
                          sb + AKV0 + s * KVSTG, tid);
        CP_COMMIT();
    }

    l0 += __shfl_xor_sync(0xFFFFFFFF, l0, 1);
    l0 += __shfl_xor_sync(0xFFFFFFFF, l0, 2);
    l1 += __shfl_xor_sync(0xFFFFFFFF, l1, 1);
    l1 += __shfl_xor_sync(0xFFFFFFFF, l1, 2);
    float inv0 = 1.0f / l0, inv1 = 1.0f / l1;

    const int g  = lane >> 2;
    const int t2 = (lane & 3) * 2;
    const int row0 = qbase + wid * 16 + g;
#pragma unroll
    for (int nf = 0; nf < 8; nf++) {
        size_t col = colbase + nf * 8 + t2;
        uint32_t hi, lo;
        split2h(o[nf][0] * inv0, o[nf][1] * inv0, hi, lo);
        *(uint32_t*)(g_Ahi + (size_t)row0 * HID + col) = hi;
        *(uint32_t*)(g_Alo + (size_t)row0 * HID + col) = lo;
        split2h(o[nf][2] * inv1, o[nf][3] * inv1, hi, lo);
        *(uint32_t*)(g_Ahi + (size_t)(row0 + 8) * HID + col) = hi;
        *(uint32_t*)(g_Alo + (size_t)(row0 + 8) * HID + col) = lo;
    }
}

// ============================================================================
// launch
// ============================================================================
extern "C" void kernel_launch(void* const* d_in, const int* in_sizes, int n_in,
                              void* d_out, int out_size) {
    (void)in_sizes; (void)n_in; (void)out_size;
    const float* query = (const float*)d_in[0];
    const float* key   = (const float*)d_in[1];
    const float* value = (const float*)d_in[2];
    const float* Wq    = (const float*)d_in[3];
    const float* bq    = (const float*)d_in[4];
    const float* Wk    = (const float*)d_in[5];
    const float* bk    = (const float*)d_in[6];
    const float* Wv    = (const float*)d_in[7];
    const float* bv    = (const float*)d_in[8];
    const float* Wo    = (const float*)d_in[9];
    const float* bo    = (const float*)d_in[10];
    float* out = (float*)d_out;

    __half *Qh, *Ql, *Kh, *Vh, *Ahi, *Alo, *Wqh, *Wkh, *Wvh, *Woh;
    cudaGetSymbolAddress((void**)&Qh, g_Qh);   cudaGetSymbolAddress((void**)&Ql, g_Ql);
    cudaGetSymbolAddress((void**)&Kh, g_Kh);   cudaGetSymbolAddress((void**)&Vh, g_Vh);
    cudaGetSymbolAddress((void**)&Ahi, g_Ahi); cudaGetSymbolAddress((void**)&Alo, g_Alo);
    cudaGetSymbolAddress((void**)&Wqh, g_Wqh); cudaGetSymbolAddress((void**)&Wkh, g_Wkh);
    cudaGetSymbolAddress((void**)&Wvh, g_Wvh); cudaGetSymbolAddress((void**)&Woh, g_Woh);

    cudaFuncSetAttribute(gemm_qkv<true>,  cudaFuncAttributeMaxDynamicSharedMemorySize, GEMM_SMEM);
    cudaFuncSetAttribute(gemm_qkv<false>, cudaFuncAttributeMaxDynamicSharedMemorySize, GEMM_SMEM);
    cudaFuncSetAttribute(gemm_out, cudaFuncAttributeMaxDynamicSharedMemorySize, GEMM_SMEM);
    cudaFuncSetAttribute(attn_mma, cudaFuncAttributeMaxDynamicSharedMemorySize, ATTN_SMEM);

    dim3 ggrid(HID / 128, MROWS / 128);
    const int wblocks = (HID * HID / 8) / 256;   // 512

    make_invf_kernel<<<1, 512>>>();
    rope_table_kernel<<<(SEQ * 512) / 256, 256>>>();

    prep_w_rowperm<<<wblocks, 256>>>(Wq, Wqh);
    prep_w_rowperm<<<wblocks, 256>>>(Wk, Wkh);
    prep_w_rowperm<<<wblocks, 256>>>(Wv, Wvh);
    prep_w_colperm<<<wblocks, 256>>>(Wo, Woh);

    gemm_qkv<true> <<<ggrid, 256, GEMM_SMEM>>>(query, Wqh, bq, Qh, Ql, 0.125f);
    gemm_qkv<false><<<ggrid, 256, GEMM_SMEM>>>(key,   Wkh, bk, Kh, nullptr, 1.0f);
    gemm_qkv<false><<<ggrid, 256, GEMM_SMEM>>>(value, Wvh, bv, Vh, nullptr, 1.0f);

    attn_mma<<<dim3(8, 128), 256, ATTN_SMEM>>>();

    gemm_out<<<ggrid, 256, GEMM_SMEM>>>(Ahi, Alo, Woh, bo, out);
}